// round 2
// baseline (speedup 1.0000x reference)
#include <cuda_runtime.h>
#include <math.h>

#define BATCH 16
#define CH    256
#define NPIX  4096            // H*W = 64*64
#define CN    (CH * NPIX)     // per-batch elements
#define BK    32

// Scratch (device globals: allocation-free per harness rules)
__device__ float g_inv1[BATCH * CH];
__device__ float g_inv2[BATCH * CH];
__device__ float g_S1[BATCH * CH * CH];   // 4 MiB: gram sums, then softmax A1 in place
__device__ float g_S2[BATCH * CH * CH];   // 4 MiB

// ---------------------------------------------------------------------------
// Kernel 1: per-row inverse L2 norms over N=4096 for both inputs.
// grid = B*C blocks, 256 threads.
// ---------------------------------------------------------------------------
__global__ __launch_bounds__(256) void norms_kernel(const float* __restrict__ x1,
                                                    const float* __restrict__ x2) {
    const int row = blockIdx.x;                     // b*C + c
    const float4* p1 = (const float4*)(x1 + (size_t)row * NPIX);
    const float4* p2 = (const float4*)(x2 + (size_t)row * NPIX);
    float s1 = 0.f, s2 = 0.f;
    for (int i = threadIdx.x; i < NPIX / 4; i += 256) {
        float4 a = p1[i];
        s1 += a.x * a.x + a.y * a.y + a.z * a.z + a.w * a.w;
        float4 b = p2[i];
        s2 += b.x * b.x + b.y * b.y + b.z * b.z + b.w * b.w;
    }
    __shared__ float sh1[8], sh2[8];
    const int lane = threadIdx.x & 31, w = threadIdx.x >> 5;
    #pragma unroll
    for (int o = 16; o; o >>= 1) {
        s1 += __shfl_xor_sync(0xffffffffu, s1, o);
        s2 += __shfl_xor_sync(0xffffffffu, s2, o);
    }
    if (lane == 0) { sh1[w] = s1; sh2[w] = s2; }
    __syncthreads();
    if (threadIdx.x == 0) {
        float t1 = 0.f, t2 = 0.f;
        #pragma unroll
        for (int i = 0; i < 8; i++) { t1 += sh1[i]; t2 += sh2[i]; }
        g_inv1[row] = 1.f / fmaxf(sqrtf(t1), 1e-12f);
        g_inv2[row] = 1.f / fmaxf(sqrtf(t2), 1e-12f);
    }
}

// ---------------------------------------------------------------------------
// Kernel 2: gram matmuls.
//   s[c,n] = inv1[c]*x1[c,n] + inv2[c]*x2[c,n]
//   S1[c,d] = inv1[d] * sum_n s[c,n]*x1[d,n]
//   S2[c,d] = inv2[d] * sum_n s[c,n]*x2[d,n]
// grid = (4 d-tiles, 4 c-tiles, B), 256 threads, 64x64 tile, 4x4 per thread.
// ---------------------------------------------------------------------------
__global__ __launch_bounds__(256) void gram_kernel(const float* __restrict__ x1,
                                                   const float* __restrict__ x2) {
    __shared__ float s_s [64][BK + 4];   // row-major (c)
    __shared__ float d1_s[BK][68];       // K-major (d contiguous)
    __shared__ float d2_s[BK][68];

    const int b  = blockIdx.z;
    const int c0 = blockIdx.y * 64;
    const int d0 = blockIdx.x * 64;
    const int t  = threadIdx.x;
    const int tx = t & 15, ty = t >> 4;
    const int ty4 = ty * 4, tx4 = tx * 4;

    const float* X1 = x1 + (size_t)b * CN;
    const float* X2 = x2 + (size_t)b * CN;
    const float* inv1 = g_inv1 + b * CH;
    const float* inv2 = g_inv2 + b * CH;

    float acc1[4][4] = {}, acc2[4][4] = {};

    for (int kk = 0; kk < NPIX; kk += BK) {
        #pragma unroll
        for (int u = 0; u < 2; u++) {
            const int v  = t + u * 256;         // 0..511
            const int r  = v >> 3;              // tile row 0..63
            const int kq = (v & 7) * 4;         // k offset (float4)
            // s tile (rows c0+r), fuse the normalization scales
            {
                const int gc = c0 + r;
                const float4 a = *(const float4*)(X1 + (size_t)gc * NPIX + kk + kq);
                const float4 bb = *(const float4*)(X2 + (size_t)gc * NPIX + kk + kq);
                const float i1 = inv1[gc], i2 = inv2[gc];
                float4 s4;
                s4.x = i1 * a.x + i2 * bb.x;
                s4.y = i1 * a.y + i2 * bb.y;
                s4.z = i1 * a.z + i2 * bb.z;
                s4.w = i1 * a.w + i2 * bb.w;
                *(float4*)&s_s[r][kq] = s4;
            }
            // d tiles (rows d0+r), raw, transposed into K-major smem
            {
                const int gd = d0 + r;
                const float4 c4 = *(const float4*)(X1 + (size_t)gd * NPIX + kk + kq);
                const float4 e4 = *(const float4*)(X2 + (size_t)gd * NPIX + kk + kq);
                d1_s[kq + 0][r] = c4.x; d1_s[kq + 1][r] = c4.y;
                d1_s[kq + 2][r] = c4.z; d1_s[kq + 3][r] = c4.w;
                d2_s[kq + 0][r] = e4.x; d2_s[kq + 1][r] = e4.y;
                d2_s[kq + 2][r] = e4.z; d2_s[kq + 3][r] = e4.w;
            }
        }
        __syncthreads();
        #pragma unroll
        for (int k = 0; k < BK; k++) {
            float sf[4];
            #pragma unroll
            for (int i = 0; i < 4; i++) sf[i] = s_s[ty4 + i][k];
            const float4 f1 = *(const float4*)&d1_s[k][tx4];
            const float4 f2 = *(const float4*)&d2_s[k][tx4];
            #pragma unroll
            for (int i = 0; i < 4; i++) {
                acc1[i][0] += sf[i] * f1.x; acc1[i][1] += sf[i] * f1.y;
                acc1[i][2] += sf[i] * f1.z; acc1[i][3] += sf[i] * f1.w;
                acc2[i][0] += sf[i] * f2.x; acc2[i][1] += sf[i] * f2.y;
                acc2[i][2] += sf[i] * f2.z; acc2[i][3] += sf[i] * f2.w;
            }
        }
        __syncthreads();
    }

    // epilogue: apply column scales, store
    const int db = d0 + tx4;
    const float4 iv1 = *(const float4*)&inv1[db];
    const float4 iv2 = *(const float4*)&inv2[db];
    #pragma unroll
    for (int i = 0; i < 4; i++) {
        const int c = c0 + ty4 + i;
        float4 r1, r2;
        r1.x = acc1[i][0] * iv1.x; r1.y = acc1[i][1] * iv1.y;
        r1.z = acc1[i][2] * iv1.z; r1.w = acc1[i][3] * iv1.w;
        r2.x = acc2[i][0] * iv2.x; r2.y = acc2[i][1] * iv2.y;
        r2.z = acc2[i][2] * iv2.z; r2.w = acc2[i][3] * iv2.w;
        *(float4*)&g_S1[((size_t)(b * CH + c)) * CH + db] = r1;
        *(float4*)&g_S2[((size_t)(b * CH + c)) * CH + db] = r2;
    }
}

// ---------------------------------------------------------------------------
// Kernel 3: row softmax of S1 and S2 in place. grid = B*C rows, 256 threads.
// ---------------------------------------------------------------------------
__global__ __launch_bounds__(256) void softmax_kernel() {
    const int row = blockIdx.x;                  // b*C + c
    const int t = threadIdx.x;
    const int lane = t & 31, w = t >> 5;
    __shared__ float sh1[8], sh2[8];
    const size_t base = (size_t)row * CH;
    const float v1 = g_S1[base + t];
    const float v2 = g_S2[base + t];

    float m1 = v1, m2 = v2;
    #pragma unroll
    for (int o = 16; o; o >>= 1) {
        m1 = fmaxf(m1, __shfl_xor_sync(0xffffffffu, m1, o));
        m2 = fmaxf(m2, __shfl_xor_sync(0xffffffffu, m2, o));
    }
    if (lane == 0) { sh1[w] = m1; sh2[w] = m2; }
    __syncthreads();
    m1 = sh1[0]; m2 = sh2[0];
    #pragma unroll
    for (int i = 1; i < 8; i++) { m1 = fmaxf(m1, sh1[i]); m2 = fmaxf(m2, sh2[i]); }

    const float e1 = __expf(v1 - m1);
    const float e2 = __expf(v2 - m2);
    __syncthreads();

    float s1 = e1, s2 = e2;
    #pragma unroll
    for (int o = 16; o; o >>= 1) {
        s1 += __shfl_xor_sync(0xffffffffu, s1, o);
        s2 += __shfl_xor_sync(0xffffffffu, s2, o);
    }
    if (lane == 0) { sh1[w] = s1; sh2[w] = s2; }
    __syncthreads();
    s1 = 0.f; s2 = 0.f;
    #pragma unroll
    for (int i = 0; i < 8; i++) { s1 += sh1[i]; s2 += sh2[i]; }

    g_S1[base + t] = e1 / s1;
    g_S2[base + t] = e2 / s2;
}

// ---------------------------------------------------------------------------
// Kernel 4: Z = A1 @ X1 + A2 @ X2  (per batch, [256 x 4096], K=256),
// then transposed residual write: out[b, n*C + d] = Z[d,n] + x1[b,f] + x2[b,f].
// grid = (64 n-tiles, 4 d-tiles, B), 256 threads, 64x64 tile.
// ---------------------------------------------------------------------------
__global__ __launch_bounds__(256) void out_kernel(const float* __restrict__ x1,
                                                  const float* __restrict__ x2,
                                                  float* __restrict__ out) {
    __shared__ float smem_raw[2 * 64 * 36 + 2 * BK * 68];   // 35840 B
    float (*A1s)[36] = (float(*)[36])smem_raw;
    float (*A2s)[36] = (float(*)[36])(smem_raw + 64 * 36);
    float (*X1s)[68] = (float(*)[68])(smem_raw + 2 * 64 * 36);
    float (*X2s)[68] = (float(*)[68])(smem_raw + 2 * 64 * 36 + BK * 68);

    const int b  = blockIdx.z;
    const int d0 = blockIdx.y * 64;
    const int n0 = blockIdx.x * 64;
    const int t  = threadIdx.x;
    const int tx = t & 15, ty = t >> 4;
    const int ty4 = ty * 4, tx4 = tx * 4;

    const float* A1 = g_S1 + (size_t)b * CH * CH;
    const float* A2 = g_S2 + (size_t)b * CH * CH;
    const float* X1 = x1 + (size_t)b * CN;
    const float* X2 = x2 + (size_t)b * CN;

    float acc[4][4] = {};   // acc[i][j]: d = d0+ty4+i (output row c), n = n0+tx4+j

    for (int kk = 0; kk < CH; kk += BK) {
        #pragma unroll
        for (int u = 0; u < 2; u++) {
            const int v = t + u * 256;           // 0..511
            {   // A tiles: 64 rows (d) x 32 (k), natural layout
                const int r = v >> 3, kq = (v & 7) * 4;
                *(float4*)&A1s[r][kq] = *(const float4*)(A1 + (size_t)(d0 + r) * CH + kk + kq);
                *(float4*)&A2s[r][kq] = *(const float4*)(A2 + (size_t)(d0 + r) * CH + kk + kq);
            }
            {   // X tiles: 32 rows (k) x 64 (n), natural (already K-major)
                const int r = v >> 4, nq = (v & 15) * 4;
                *(float4*)&X1s[r][nq] = *(const float4*)(X1 + (size_t)(kk + r) * NPIX + n0 + nq);
                *(float4*)&X2s[r][nq] = *(const float4*)(X2 + (size_t)(kk + r) * NPIX + n0 + nq);
            }
        }
        __syncthreads();
        #pragma unroll
        for (int k = 0; k < BK; k++) {
            float a1[4], a2[4];
            #pragma unroll
            for (int i = 0; i < 4; i++) { a1[i] = A1s[ty4 + i][k]; a2[i] = A2s[ty4 + i][k]; }
            const float4 f1 = *(const float4*)&X1s[k][tx4];
            const float4 f2 = *(const float4*)&X2s[k][tx4];
            #pragma unroll
            for (int i = 0; i < 4; i++) {
                acc[i][0] += a1[i] * f1.x + a2[i] * f2.x;
                acc[i][1] += a1[i] * f1.y + a2[i] * f2.y;
                acc[i][2] += a1[i] * f1.z + a2[i] * f2.z;
                acc[i][3] += a1[i] * f1.w + a2[i] * f2.w;
            }
        }
        __syncthreads();
    }

    // Stage Z into smem (reuse tile space) and do the transposed residual write.
    float (*Zs)[65] = (float(*)[65])smem_raw;   // [n][d], 64*65 = 4160 floats
    #pragma unroll
    for (int i = 0; i < 4; i++)
        #pragma unroll
        for (int j = 0; j < 4; j++)
            Zs[tx4 + j][ty4 + i] = acc[i][j];
    __syncthreads();

    #pragma unroll
    for (int r = 0; r < 16; r++) {
        const int e = t + r * 256;               // 0..4095
        const int d = e & 63, n = e >> 6;
        const size_t f = (size_t)(n0 + n) * CH + d0 + d;   // out flat index within batch
        const size_t g = (size_t)b * CN + f;
        out[g] = Zs[n][d] + x1[g] + x2[g];
    }
}

// ---------------------------------------------------------------------------
extern "C" void kernel_launch(void* const* d_in, const int* in_sizes, int n_in,
                              void* d_out, int out_size) {
    (void)in_sizes; (void)n_in; (void)out_size;
    const float* x1 = (const float*)d_in[0];
    const float* x2 = (const float*)d_in[1];
    float* out = (float*)d_out;

    norms_kernel<<<BATCH * CH, 256>>>(x1, x2);
    gram_kernel<<<dim3(4, 4, BATCH), 256>>>(x1, x2);
    softmax_kernel<<<BATCH * CH, 256>>>();
    out_kernel<<<dim3(64, 4, BATCH), 256>>>(x1, x2, out);
}

// round 4
// speedup vs baseline: 3.7118x; 3.7118x over previous
#include <cuda_runtime.h>
#include <cuda_bf16.h>
#include <math.h>
#include <stdint.h>

#define BATCH 16
#define CH    256
#define NPIX  4096
#define CN    (CH * NPIX)

typedef __nv_bfloat16 bf16;

// ---------------- device-global scratch (allocation-free) ----------------
__device__ float g_inv1[BATCH * CH];
__device__ float g_inv2[BATCH * CH];
__device__ __align__(16) bf16 g_s  [BATCH * CN];   // inv1*x1+inv2*x2 [b][c][n]
__device__ __align__(16) bf16 g_n1 [BATCH * CN];   // inv1*x1         [b][c][n]
__device__ __align__(16) bf16 g_n2 [BATCH * CN];   // inv2*x2         [b][c][n]
__device__ __align__(16) bf16 g_rT1[BATCH * CN];   // raw x1 T        [b][n][c]
__device__ __align__(16) bf16 g_rT2[BATCH * CN];   // raw x2 T        [b][n][c]
__device__ __align__(16) float g_S1[BATCH * CH * CH];  // fp32 logits [b][c][d]
__device__ __align__(16) float g_S2[BATCH * CH * CH];
__device__ __align__(16) bf16 g_A1 [BATCH * CH * CH];  // bf16 probs  [b][c][d]
__device__ __align__(16) bf16 g_A2 [BATCH * CH * CH];

// ---------------- PTX helpers (family-portable: sm_80+ baseline) ----------
__device__ __forceinline__ uint32_t smem_u32(const void* p) {
    uint32_t a;
    asm("{ .reg .u64 t; cvta.to.shared.u64 t, %1; cvt.u32.u64 %0, t; }" : "=r"(a) : "l"(p));
    return a;
}
__device__ __forceinline__ void cpasync16(uint32_t s, const void* g) {
    asm volatile("cp.async.cg.shared.global [%0], [%1], 16;" :: "r"(s), "l"(g));
}
#define CP_COMMIT() asm volatile("cp.async.commit_group;")
#define CP_WAIT(N)  asm volatile("cp.async.wait_group %0;" :: "n"(N))

__device__ __forceinline__ void ldm_x4(uint32_t* r, uint32_t a) {
    asm volatile("ldmatrix.sync.aligned.m8n8.x4.shared.b16 {%0,%1,%2,%3}, [%4];"
        : "=r"(r[0]), "=r"(r[1]), "=r"(r[2]), "=r"(r[3]) : "r"(a));
}
__device__ __forceinline__ void mma16816(float* c, const uint32_t* a, const uint32_t* b) {
    asm volatile("mma.sync.aligned.m16n8k16.row.col.f32.bf16.bf16.f32 "
        "{%0,%1,%2,%3}, {%4,%5,%6,%7}, {%8,%9}, {%0,%1,%2,%3};"
        : "+f"(c[0]), "+f"(c[1]), "+f"(c[2]), "+f"(c[3])
        : "r"(a[0]), "r"(a[1]), "r"(a[2]), "r"(a[3]), "r"(b[0]), "r"(b[1]));
}

// smem tile geometry: 128 rows x 32 bf16, padded row = 40 elems (80B).
// 80/16 = 5 (odd) -> ldmatrix 8-row gathers are bank-conflict-free.
#define ROW_B   80
#define TILE_B  (128 * ROW_B)        // 10240 B
#define STAGE_B (2 * TILE_B)         // A + B per stage

// ---------------------------------------------------------------------------
// Shared mainloop: C[128(m) x 128(n)] += A[m,k] * B[n,k]^T over niter*32 k.
// A row-major lda, B row-major ldb (i.e. col-major k x n). Double-buffered
// cp.async pipeline. 8 warps: warp tile 64(m) x 32(n).
// ---------------------------------------------------------------------------
__device__ __forceinline__ void gemm_mainloop(const bf16* __restrict__ Ag, int lda,
                                              const bf16* __restrict__ Bg, int ldb,
                                              int niter, uint32_t smb,
                                              float acc[4][4][4]) {
    const int t = threadIdx.x;
    const int w = t >> 5, l = t & 31;
    const int mw0 = (w >> 2) * 64, nw0 = (w & 3) * 32;

    // tile-fill coords: thread covers rows fr and fr+64 at 16B col fkB
    const int fr  = t >> 2;
    const int fkB = (t & 3) * 16;
    const int fkE = (t & 3) * 8;

    // ldmatrix lane coords
    const int lA_row = l & 15, lA_k = (l >> 4) * 8;
    const int q = l >> 3;
    const int lB_row = ((q >> 1) * 8) + (l & 7);
    const int lB_k = (q & 1) * 8;

    // prologue: chunk 0 -> stage 0
    {
        const bf16* ga = Ag + (size_t)fr * lda + fkE;
        const bf16* gb = Bg + (size_t)fr * ldb + fkE;
        const uint32_t sa = smb + fr * ROW_B + fkB;
        const uint32_t sb = smb + TILE_B + fr * ROW_B + fkB;
        cpasync16(sa, ga);
        cpasync16(sa + 64 * ROW_B, ga + (size_t)64 * lda);
        cpasync16(sb, gb);
        cpasync16(sb + 64 * ROW_B, gb + (size_t)64 * ldb);
        CP_COMMIT();
    }

    #pragma unroll 1
    for (int it = 0; it < niter; it++) {
        if (it + 1 < niter) {
            const int k0 = (it + 1) * 32;
            const uint32_t st = smb + ((it + 1) & 1) * STAGE_B;
            const bf16* ga = Ag + (size_t)fr * lda + k0 + fkE;
            const bf16* gb = Bg + (size_t)fr * ldb + k0 + fkE;
            const uint32_t sa = st + fr * ROW_B + fkB;
            const uint32_t sb = st + TILE_B + fr * ROW_B + fkB;
            cpasync16(sa, ga);
            cpasync16(sa + 64 * ROW_B, ga + (size_t)64 * lda);
            cpasync16(sb, gb);
            cpasync16(sb + 64 * ROW_B, gb + (size_t)64 * ldb);
            CP_COMMIT();
            CP_WAIT(1);
        } else {
            CP_WAIT(0);
        }
        __syncthreads();

        const uint32_t Abase = smb + (it & 1) * STAGE_B;
        const uint32_t Bbase = Abase + TILE_B;
        #pragma unroll
        for (int ks = 0; ks < 2; ks++) {
            uint32_t afr[4][4], bfr[4][2];
            #pragma unroll
            for (int i = 0; i < 4; i++)
                ldm_x4(afr[i], Abase + (mw0 + i * 16 + lA_row) * ROW_B
                                     + (ks * 16 + lA_k) * 2);
            #pragma unroll
            for (int p = 0; p < 2; p++) {
                uint32_t r[4];
                ldm_x4(r, Bbase + (nw0 + p * 16 + lB_row) * ROW_B
                                + (ks * 16 + lB_k) * 2);
                bfr[p * 2][0] = r[0]; bfr[p * 2][1] = r[1];
                bfr[p * 2 + 1][0] = r[2]; bfr[p * 2 + 1][1] = r[3];
            }
            #pragma unroll
            for (int i = 0; i < 4; i++)
                #pragma unroll
                for (int j = 0; j < 4; j++)
                    mma16816(acc[i][j], afr[i], bfr[j]);
        }
        __syncthreads();
    }
}

// ---------------------------------------------------------------------------
// Kernel 1: per-row inverse L2 norms.
// ---------------------------------------------------------------------------
__global__ __launch_bounds__(256) void norms_kernel(const float* __restrict__ x1,
                                                    const float* __restrict__ x2) {
    const int row = blockIdx.x;
    const float4* p1 = (const float4*)(x1 + (size_t)row * NPIX);
    const float4* p2 = (const float4*)(x2 + (size_t)row * NPIX);
    float s1 = 0.f, s2 = 0.f;
    for (int i = threadIdx.x; i < NPIX / 4; i += 256) {
        float4 a = p1[i];
        s1 += a.x * a.x + a.y * a.y + a.z * a.z + a.w * a.w;
        float4 b = p2[i];
        s2 += b.x * b.x + b.y * b.y + b.z * b.z + b.w * b.w;
    }
    __shared__ float sh1[8], sh2[8];
    const int lane = threadIdx.x & 31, w = threadIdx.x >> 5;
    #pragma unroll
    for (int o = 16; o; o >>= 1) {
        s1 += __shfl_xor_sync(0xffffffffu, s1, o);
        s2 += __shfl_xor_sync(0xffffffffu, s2, o);
    }
    if (lane == 0) { sh1[w] = s1; sh2[w] = s2; }
    __syncthreads();
    if (threadIdx.x == 0) {
        float t1 = 0.f, t2 = 0.f;
        #pragma unroll
        for (int i = 0; i < 8; i++) { t1 += sh1[i]; t2 += sh2[i]; }
        g_inv1[row] = 1.f / fmaxf(sqrtf(t1), 1e-12f);
        g_inv2[row] = 1.f / fmaxf(sqrtf(t2), 1e-12f);
    }
}

// ---------------------------------------------------------------------------
// Kernel 2: bf16 conversion + transpose. grid (64 n-tiles, 4 c-tiles, B).
// ---------------------------------------------------------------------------
__global__ __launch_bounds__(256) void convert_kernel(const float* __restrict__ x1,
                                                      const float* __restrict__ x2) {
    __shared__ bf16 smT1[64][68];
    __shared__ bf16 smT2[64][68];
    const int b = blockIdx.z, c0 = blockIdx.y * 64, n0 = blockIdx.x * 64;
    const int t = threadIdx.x;
    const int row = t >> 2, q = t & 3;
    const int c = c0 + row;
    const float i1 = g_inv1[b * CH + c], i2 = g_inv2[b * CH + c];
    const size_t base = (size_t)(b * CH + c) * NPIX + n0;
    #pragma unroll
    for (int p = 0; p < 4; p++) {
        const int nq = p * 16 + q * 4;
        const float4 f1 = *(const float4*)(x1 + base + nq);
        const float4 f2 = *(const float4*)(x2 + base + nq);
        const float a[4]  = {f1.x, f1.y, f1.z, f1.w};
        const float bb[4] = {f2.x, f2.y, f2.z, f2.w};
        bf16 n1v[4], n2v[4], sv[4];
        #pragma unroll
        for (int i = 0; i < 4; i++) {
            n1v[i] = __float2bfloat16(i1 * a[i]);
            n2v[i] = __float2bfloat16(i2 * bb[i]);
            sv[i]  = __float2bfloat16(i1 * a[i] + i2 * bb[i]);
            smT1[nq + i][row] = __float2bfloat16(a[i]);
            smT2[nq + i][row] = __float2bfloat16(bb[i]);
        }
        *(uint2*)(g_n1 + base + nq) = *(const uint2*)n1v;
        *(uint2*)(g_n2 + base + nq) = *(const uint2*)n2v;
        *(uint2*)(g_s  + base + nq) = *(const uint2*)sv;
    }
    __syncthreads();
    const int nl = row;
    const size_t tbase = ((size_t)b * NPIX + n0 + nl) * CH + c0 + q * 16;
    const uint2* s1 = (const uint2*)&smT1[nl][q * 16];
    const uint2* s2 = (const uint2*)&smT2[nl][q * 16];
    #pragma unroll
    for (int i = 0; i < 4; i++) {
        ((uint2*)(g_rT1 + tbase))[i] = s1[i];
        ((uint2*)(g_rT2 + tbase))[i] = s2[i];
    }
}

// ---------------------------------------------------------------------------
// Kernel 3: gram HMMA. S{mat}[c,d] = sum_n s[c,n]*n{mat}[d,n], fp32 out.
// grid (2 dblk, 2 cblk, B*2). smem = 2 stages * 20480 = 40960 B.
// ---------------------------------------------------------------------------
__global__ __launch_bounds__(256) void gram_mma() {
    extern __shared__ char sm[];
    const uint32_t smb = smem_u32(sm);
    const int t = threadIdx.x, w = t >> 5, l = t & 31;
    const int dblk = blockIdx.x, cblk = blockIdx.y;
    const int b = blockIdx.z >> 1, mat = blockIdx.z & 1;

    const bf16* Ag = g_s + (size_t)b * CN + (size_t)(cblk * 128) * NPIX;
    const bf16* Bg = (mat ? g_n2 : g_n1) + (size_t)b * CN + (size_t)(dblk * 128) * NPIX;

    float acc[4][4][4] = {};
    gemm_mainloop(Ag, NPIX, Bg, NPIX, NPIX / 32, smb, acc);

    float* S = (mat ? g_S2 : g_S1) + (size_t)(b * CH + cblk * 128) * CH + dblk * 128;
    const int mw0 = (w >> 2) * 64, nw0 = (w & 3) * 32;
    const int rr = l >> 2, cc = (l & 3) * 2;
    #pragma unroll
    for (int i = 0; i < 4; i++)
        #pragma unroll
        for (int j = 0; j < 4; j++) {
            const int c_ = mw0 + i * 16 + rr;
            const int d_ = nw0 + j * 8 + cc;
            float2 lo = {acc[i][j][0], acc[i][j][1]};
            float2 hi = {acc[i][j][2], acc[i][j][3]};
            *(float2*)&S[(size_t)c_ * CH + d_] = lo;
            *(float2*)&S[(size_t)(c_ + 8) * CH + d_] = hi;
        }
}

// ---------------------------------------------------------------------------
// Kernel 4: row softmax fp32 S -> bf16 A. grid = B*CH rows, 256 threads.
// ---------------------------------------------------------------------------
__global__ __launch_bounds__(256) void softmax_kernel() {
    const int row = blockIdx.x;
    const int t = threadIdx.x;
    const int lane = t & 31, w = t >> 5;
    __shared__ float sh1[8], sh2[8];
    const size_t base = (size_t)row * CH;
    const float v1 = g_S1[base + t];
    const float v2 = g_S2[base + t];

    float m1 = v1, m2 = v2;
    #pragma unroll
    for (int o = 16; o; o >>= 1) {
        m1 = fmaxf(m1, __shfl_xor_sync(0xffffffffu, m1, o));
        m2 = fmaxf(m2, __shfl_xor_sync(0xffffffffu, m2, o));
    }
    if (lane == 0) { sh1[w] = m1; sh2[w] = m2; }
    __syncthreads();
    m1 = sh1[0]; m2 = sh2[0];
    #pragma unroll
    for (int i = 1; i < 8; i++) { m1 = fmaxf(m1, sh1[i]); m2 = fmaxf(m2, sh2[i]); }

    const float e1 = __expf(v1 - m1);
    const float e2 = __expf(v2 - m2);
    __syncthreads();

    float s1 = e1, s2 = e2;
    #pragma unroll
    for (int o = 16; o; o >>= 1) {
        s1 += __shfl_xor_sync(0xffffffffu, s1, o);
        s2 += __shfl_xor_sync(0xffffffffu, s2, o);
    }
    if (lane == 0) { sh1[w] = s1; sh2[w] = s2; }
    __syncthreads();
    s1 = 0.f; s2 = 0.f;
    #pragma unroll
    for (int i = 0; i < 8; i++) { s1 += sh1[i]; s2 += sh2[i]; }

    g_A1[base + t] = __float2bfloat16(e1 / s1);
    g_A2[base + t] = __float2bfloat16(e2 / s2);
}

// ---------------------------------------------------------------------------
// Kernel 5: back-projection HMMA + residual.
// Z[c,n] = sum_d A1[c,d]*rT1[n,d] + A2[c,d]*rT2[n,d];
// out[b, n*CH + c] = Z + x1 + x2.
// grid (32 nblk, 2 cblk, B). smem = max(40960, 73728) = 73728 B.
// ---------------------------------------------------------------------------
__global__ __launch_bounds__(256) void out_mma(const float* __restrict__ x1,
                                               const float* __restrict__ x2,
                                               float* __restrict__ out) {
    extern __shared__ char sm[];
    const uint32_t smb = smem_u32(sm);
    const int t = threadIdx.x, w = t >> 5, l = t & 31;
    const int nblk = blockIdx.x, cblk = blockIdx.y, b = blockIdx.z;
    const int n0 = nblk * 128, c0 = cblk * 128;

    const bf16* A1g = g_A1 + (size_t)(b * CH + c0) * CH;
    const bf16* A2g = g_A2 + (size_t)(b * CH + c0) * CH;
    const bf16* B1g = g_rT1 + ((size_t)b * NPIX + n0) * CH;
    const bf16* B2g = g_rT2 + ((size_t)b * NPIX + n0) * CH;

    float acc[4][4][4] = {};
    gemm_mainloop(A1g, CH, B1g, CH, CH / 32, smb, acc);
    gemm_mainloop(A2g, CH, B2g, CH, CH / 32, smb, acc);
    __syncthreads();

    // stage Z into smem: per-warp region [32 n][72 c] fp32
    float* reg = (float*)sm + w * (32 * 72);
    const int rr = l >> 2, cc = (l & 3) * 2;
    #pragma unroll
    for (int i = 0; i < 4; i++)
        #pragma unroll
        for (int j = 0; j < 4; j++) {
            const int cl = i * 16 + rr;
            const int nl = j * 8 + cc;
            reg[nl * 72 + cl]           = acc[i][j][0];
            reg[(nl + 1) * 72 + cl]     = acc[i][j][1];
            reg[nl * 72 + cl + 8]       = acc[i][j][2];
            reg[(nl + 1) * 72 + cl + 8] = acc[i][j][3];
        }
    __syncthreads();

    // coalesced residual write: warp w handles rows nn = p*8 + w
    #pragma unroll 1
    for (int p = 0; p < 16; p++) {
        const int nn = p * 8 + w;
        const int c4 = l * 4;
        const float* src = (const float*)sm
            + ((c4 >> 6) * 4 + (nn >> 5)) * (32 * 72)
            + (nn & 31) * 72 + (c4 & 63);
        const float4 z = *(const float4*)src;
        const size_t g = (size_t)b * CN + (size_t)(n0 + nn) * CH + c0 + c4;
        const float4 a = *(const float4*)(x1 + g);
        const float4 bb = *(const float4*)(x2 + g);
        float4 o;
        o.x = z.x + a.x + bb.x; o.y = z.y + a.y + bb.y;
        o.z = z.z + a.z + bb.z; o.w = z.w + a.w + bb.w;
        *(float4*)(out + g) = o;
    }
}

// ---------------------------------------------------------------------------
extern "C" void kernel_launch(void* const* d_in, const int* in_sizes, int n_in,
                              void* d_out, int out_size) {
    (void)in_sizes; (void)n_in; (void)out_size;
    const float* x1 = (const float*)d_in[0];
    const float* x2 = (const float*)d_in[1];
    float* out = (float*)d_out;

    cudaFuncSetAttribute(gram_mma, cudaFuncAttributeMaxDynamicSharedMemorySize, 2 * STAGE_B);
    cudaFuncSetAttribute(out_mma,  cudaFuncAttributeMaxDynamicSharedMemorySize, 73728);

    norms_kernel<<<BATCH * CH, 256>>>(x1, x2);
    convert_kernel<<<dim3(64, 4, BATCH), 256>>>(x1, x2);
    gram_mma<<<dim3(2, 2, BATCH * 2), 256, 2 * STAGE_B>>>();
    softmax_kernel<<<BATCH * CH, 256>>>();
    out_mma<<<dim3(32, 2, BATCH), 256, 73728>>>(x1, x2, out);
}

// round 6
// speedup vs baseline: 4.2635x; 1.1486x over previous
#include <cuda_runtime.h>
#include <cuda_bf16.h>
#include <math.h>
#include <stdint.h>

#define BATCH 16
#define CH    256
#define NPIX  4096
#define CN    (CH * NPIX)

typedef __nv_bfloat16 bf16;

// ---------------- device-global scratch (allocation-free) ----------------
__device__ float g_inv1[BATCH * CH];
__device__ float g_inv2[BATCH * CH];
__device__ __align__(16) bf16 g_s  [BATCH * CN];   // inv1*x1+inv2*x2 [b][c][n]
__device__ __align__(16) bf16 g_n1 [BATCH * CN];   // inv1*x1         [b][c][n]
__device__ __align__(16) bf16 g_n2 [BATCH * CN];   // inv2*x2         [b][c][n]
__device__ __align__(16) bf16 g_rT1[BATCH * CN];   // raw x1 T        [b][n][c]
__device__ __align__(16) bf16 g_rT2[BATCH * CN];   // raw x2 T        [b][n][c]
__device__ __align__(16) float g_S1[BATCH * CH * CH];  // fp32 logits [b][c][d]
__device__ __align__(16) float g_S2[BATCH * CH * CH];
__device__ __align__(16) bf16 g_A1 [BATCH * CH * CH];  // bf16 probs  [b][c][d]
__device__ __align__(16) bf16 g_A2 [BATCH * CH * CH];

// ---------------- PTX helpers (family-portable: sm_80+ baseline) ----------
__device__ __forceinline__ uint32_t smem_u32(const void* p) {
    uint32_t a;
    asm("{ .reg .u64 t; cvta.to.shared.u64 t, %1; cvt.u32.u64 %0, t; }" : "=r"(a) : "l"(p));
    return a;
}
__device__ __forceinline__ void cpasync16(uint32_t s, const void* g) {
    asm volatile("cp.async.cg.shared.global [%0], [%1], 16;" :: "r"(s), "l"(g));
}
#define CP_COMMIT() asm volatile("cp.async.commit_group;")
#define CP_WAIT(N)  asm volatile("cp.async.wait_group %0;" :: "n"(N))

__device__ __forceinline__ void ldm_x4(uint32_t* r, uint32_t a) {
    asm volatile("ldmatrix.sync.aligned.m8n8.x4.shared.b16 {%0,%1,%2,%3}, [%4];"
        : "=r"(r[0]), "=r"(r[1]), "=r"(r[2]), "=r"(r[3]) : "r"(a));
}
__device__ __forceinline__ void mma16816(float* c, const uint32_t* a, const uint32_t* b) {
    asm volatile("mma.sync.aligned.m16n8k16.row.col.f32.bf16.bf16.f32 "
        "{%0,%1,%2,%3}, {%4,%5,%6,%7}, {%8,%9}, {%0,%1,%2,%3};"
        : "+f"(c[0]), "+f"(c[1]), "+f"(c[2]), "+f"(c[3])
        : "r"(a[0]), "r"(a[1]), "r"(a[2]), "r"(a[3]), "r"(b[0]), "r"(b[1]));
}

// smem tile geometry: 128 rows x 32 bf16, padded row = 40 elems (80B).
#define ROW_B   80
#define TILE_B  (128 * ROW_B)        // 10240 B
#define STAGE_B (2 * TILE_B)         // A + B per stage = 20480 B
#define PIPE    3
#define SM_MAIN (PIPE * STAGE_B)     // 61440 B

// ---------------------------------------------------------------------------
// Shared mainloop: C[128(m) x 128(n)] += A[m,k] * B[n,k]^T over niter*32 k.
// 3-stage cp.async pipeline. 8 warps: warp tile 64(m) x 32(n).
// ---------------------------------------------------------------------------
__device__ __forceinline__ void gemm_mainloop(const bf16* __restrict__ Ag, int lda,
                                              const bf16* __restrict__ Bg, int ldb,
                                              int niter, uint32_t smb,
                                              float acc[4][4][4]) {
    const int t = threadIdx.x;
    const int w = t >> 5, l = t & 31;
    const int mw0 = (w >> 2) * 64, nw0 = (w & 3) * 32;

    const int fr  = t >> 2;
    const int fkB = (t & 3) * 16;
    const int fkE = (t & 3) * 8;

    const int lA_row = l & 15, lA_k = (l >> 4) * 8;
    const int q = l >> 3;
    const int lB_row = ((q >> 1) * 8) + (l & 7);
    const int lB_k = (q & 1) * 8;

    // prologue: chunks 0,1 -> stages 0,1
    #pragma unroll
    for (int s = 0; s < PIPE - 1; s++) {
        const int k0 = s * 32;
        const uint32_t st = smb + s * STAGE_B;
        const bf16* ga = Ag + (size_t)fr * lda + k0 + fkE;
        const bf16* gb = Bg + (size_t)fr * ldb + k0 + fkE;
        const uint32_t sa = st + fr * ROW_B + fkB;
        const uint32_t sb = st + TILE_B + fr * ROW_B + fkB;
        cpasync16(sa, ga);
        cpasync16(sa + 64 * ROW_B, ga + (size_t)64 * lda);
        cpasync16(sb, gb);
        cpasync16(sb + 64 * ROW_B, gb + (size_t)64 * ldb);
        CP_COMMIT();
    }

    int stage = 0, nstage = PIPE - 1;
    #pragma unroll 1
    for (int it = 0; it < niter; it++) {
        if (it + PIPE - 1 < niter) {
            const int k0 = (it + PIPE - 1) * 32;
            const uint32_t st = smb + nstage * STAGE_B;
            const bf16* ga = Ag + (size_t)fr * lda + k0 + fkE;
            const bf16* gb = Bg + (size_t)fr * ldb + k0 + fkE;
            const uint32_t sa = st + fr * ROW_B + fkB;
            const uint32_t sb = st + TILE_B + fr * ROW_B + fkB;
            cpasync16(sa, ga);
            cpasync16(sa + 64 * ROW_B, ga + (size_t)64 * lda);
            cpasync16(sb, gb);
            cpasync16(sb + 64 * ROW_B, gb + (size_t)64 * ldb);
            CP_COMMIT();
            CP_WAIT(PIPE - 1);
            if (++nstage == PIPE) nstage = 0;
        } else {
            CP_WAIT(0);
        }
        __syncthreads();

        const uint32_t Abase = smb + stage * STAGE_B;
        const uint32_t Bbase = Abase + TILE_B;
        if (++stage == PIPE) stage = 0;
        #pragma unroll
        for (int ks = 0; ks < 2; ks++) {
            uint32_t afr[4][4], bfr[4][2];
            #pragma unroll
            for (int i = 0; i < 4; i++)
                ldm_x4(afr[i], Abase + (mw0 + i * 16 + lA_row) * ROW_B
                                     + (ks * 16 + lA_k) * 2);
            #pragma unroll
            for (int p = 0; p < 2; p++) {
                uint32_t r[4];
                ldm_x4(r, Bbase + (nw0 + p * 16 + lB_row) * ROW_B
                                + (ks * 16 + lB_k) * 2);
                bfr[p * 2][0] = r[0]; bfr[p * 2][1] = r[1];
                bfr[p * 2 + 1][0] = r[2]; bfr[p * 2 + 1][1] = r[3];
            }
            #pragma unroll
            for (int i = 0; i < 4; i++)
                #pragma unroll
                for (int j = 0; j < 4; j++)
                    mma16816(acc[i][j], afr[i], bfr[j]);
        }
        __syncthreads();
    }
}

// ---------------------------------------------------------------------------
// Kernel 1: per-row inverse L2 norms.
// ---------------------------------------------------------------------------
__global__ __launch_bounds__(256) void norms_kernel(const float* __restrict__ x1,
                                                    const float* __restrict__ x2) {
    const int row = blockIdx.x;
    const float4* p1 = (const float4*)(x1 + (size_t)row * NPIX);
    const float4* p2 = (const float4*)(x2 + (size_t)row * NPIX);
    float s1 = 0.f, s2 = 0.f;
    for (int i = threadIdx.x; i < NPIX / 4; i += 256) {
        float4 a = p1[i];
        s1 += a.x * a.x + a.y * a.y + a.z * a.z + a.w * a.w;
        float4 b = p2[i];
        s2 += b.x * b.x + b.y * b.y + b.z * b.z + b.w * b.w;
    }
    __shared__ float sh1[8], sh2[8];
    const int lane = threadIdx.x & 31, w = threadIdx.x >> 5;
    #pragma unroll
    for (int o = 16; o; o >>= 1) {
        s1 += __shfl_xor_sync(0xffffffffu, s1, o);
        s2 += __shfl_xor_sync(0xffffffffu, s2, o);
    }
    if (lane == 0) { sh1[w] = s1; sh2[w] = s2; }
    __syncthreads();
    if (threadIdx.x == 0) {
        float t1 = 0.f, t2 = 0.f;
        #pragma unroll
        for (int i = 0; i < 8; i++) { t1 += sh1[i]; t2 += sh2[i]; }
        g_inv1[row] = 1.f / fmaxf(sqrtf(t1), 1e-12f);
        g_inv2[row] = 1.f / fmaxf(sqrtf(t2), 1e-12f);
    }
}

// ---------------------------------------------------------------------------
// Kernel 2: bf16 conversion + transpose. grid (64 n-tiles, 4 c-tiles, B).
// ---------------------------------------------------------------------------
__global__ __launch_bounds__(256) void convert_kernel(const float* __restrict__ x1,
                                                      const float* __restrict__ x2) {
    __shared__ bf16 smT1[64][68];
    __shared__ bf16 smT2[64][68];
    const int b = blockIdx.z, c0 = blockIdx.y * 64, n0 = blockIdx.x * 64;
    const int t = threadIdx.x;
    const int row = t >> 2, q = t & 3;
    const int c = c0 + row;
    const float i1 = g_inv1[b * CH + c], i2 = g_inv2[b * CH + c];
    const size_t base = (size_t)(b * CH + c) * NPIX + n0;
    #pragma unroll
    for (int p = 0; p < 4; p++) {
        const int nq = p * 16 + q * 4;
        const float4 f1 = *(const float4*)(x1 + base + nq);
        const float4 f2 = *(const float4*)(x2 + base + nq);
        const float a[4]  = {f1.x, f1.y, f1.z, f1.w};
        const float bb[4] = {f2.x, f2.y, f2.z, f2.w};
        bf16 n1v[4], n2v[4], sv[4];
        #pragma unroll
        for (int i = 0; i < 4; i++) {
            n1v[i] = __float2bfloat16(i1 * a[i]);
            n2v[i] = __float2bfloat16(i2 * bb[i]);
            sv[i]  = __float2bfloat16(i1 * a[i] + i2 * bb[i]);
            smT1[nq + i][row] = __float2bfloat16(a[i]);
            smT2[nq + i][row] = __float2bfloat16(bb[i]);
        }
        *(uint2*)(g_n1 + base + nq) = *(const uint2*)n1v;
        *(uint2*)(g_n2 + base + nq) = *(const uint2*)n2v;
        *(uint2*)(g_s  + base + nq) = *(const uint2*)sv;
    }
    __syncthreads();
    const int nl = row;
    const size_t tbase = ((size_t)b * NPIX + n0 + nl) * CH + c0 + q * 16;
    const uint2* s1 = (const uint2*)&smT1[nl][q * 16];
    const uint2* s2 = (const uint2*)&smT2[nl][q * 16];
    #pragma unroll
    for (int i = 0; i < 4; i++) {
        ((uint2*)(g_rT1 + tbase))[i] = s1[i];
        ((uint2*)(g_rT2 + tbase))[i] = s2[i];
    }
}

// ---------------------------------------------------------------------------
// Kernel 3: gram HMMA. S{mat}[c,d] = sum_n s[c,n]*n{mat}[d,n], fp32 out.
// grid (2 dblk, 2 cblk, B*2). smem = 61440 B, target 2 CTAs/SM.
// ---------------------------------------------------------------------------
__global__ __launch_bounds__(256, 2) void gram_mma() {
    extern __shared__ char sm[];
    const uint32_t smb = smem_u32(sm);
    const int t = threadIdx.x, w = t >> 5, l = t & 31;
    const int dblk = blockIdx.x, cblk = blockIdx.y;
    const int b = blockIdx.z >> 1, mat = blockIdx.z & 1;

    const bf16* Ag = g_s + (size_t)b * CN + (size_t)(cblk * 128) * NPIX;
    const bf16* Bg = (mat ? g_n2 : g_n1) + (size_t)b * CN + (size_t)(dblk * 128) * NPIX;

    float acc[4][4][4] = {};
    gemm_mainloop(Ag, NPIX, Bg, NPIX, NPIX / 32, smb, acc);

    float* S = (mat ? g_S2 : g_S1) + (size_t)(b * CH + cblk * 128) * CH + dblk * 128;
    const int mw0 = (w >> 2) * 64, nw0 = (w & 3) * 32;
    const int rr = l >> 2, cc = (l & 3) * 2;
    #pragma unroll
    for (int i = 0; i < 4; i++)
        #pragma unroll
        for (int j = 0; j < 4; j++) {
            const int c_ = mw0 + i * 16 + rr;
            const int d_ = nw0 + j * 8 + cc;
            float2 lo = {acc[i][j][0], acc[i][j][1]};
            float2 hi = {acc[i][j][2], acc[i][j][3]};
            *(float2*)&S[(size_t)c_ * CH + d_] = lo;
            *(float2*)&S[(size_t)(c_ + 8) * CH + d_] = hi;
        }
}

// ---------------------------------------------------------------------------
// Kernel 4: row softmax fp32 S -> bf16 A. grid = B*CH rows, 256 threads.
// ---------------------------------------------------------------------------
__global__ __launch_bounds__(256) void softmax_kernel() {
    const int row = blockIdx.x;
    const int t = threadIdx.x;
    const int lane = t & 31, w = t >> 5;
    __shared__ float sh1[8], sh2[8];
    const size_t base = (size_t)row * CH;
    const float v1 = g_S1[base + t];
    const float v2 = g_S2[base + t];

    float m1 = v1, m2 = v2;
    #pragma unroll
    for (int o = 16; o; o >>= 1) {
        m1 = fmaxf(m1, __shfl_xor_sync(0xffffffffu, m1, o));
        m2 = fmaxf(m2, __shfl_xor_sync(0xffffffffu, m2, o));
    }
    if (lane == 0) { sh1[w] = m1; sh2[w] = m2; }
    __syncthreads();
    m1 = sh1[0]; m2 = sh2[0];
    #pragma unroll
    for (int i = 1; i < 8; i++) { m1 = fmaxf(m1, sh1[i]); m2 = fmaxf(m2, sh2[i]); }

    const float e1 = __expf(v1 - m1);
    const float e2 = __expf(v2 - m2);
    __syncthreads();

    float s1 = e1, s2 = e2;
    #pragma unroll
    for (int o = 16; o; o >>= 1) {
        s1 += __shfl_xor_sync(0xffffffffu, s1, o);
        s2 += __shfl_xor_sync(0xffffffffu, s2, o);
    }
    if (lane == 0) { sh1[w] = s1; sh2[w] = s2; }
    __syncthreads();
    s1 = 0.f; s2 = 0.f;
    #pragma unroll
    for (int i = 0; i < 8; i++) { s1 += sh1[i]; s2 += sh2[i]; }

    g_A1[base + t] = __float2bfloat16(e1 / s1);
    g_A2[base + t] = __float2bfloat16(e2 / s2);
}

// ---------------------------------------------------------------------------
// Kernel 5: back-projection HMMA + residual.
// Z[c,n] = sum_d A1[c,d]*rT1[n,d] + A2[c,d]*rT2[n,d];
// out[b, n*CH + c] = Z + x1 + x2.
// grid (32 nblk, 2 cblk, B). smem = 61440 B, target 2 CTAs/SM.
// Epilogue stages Z through smem in two 64-n halves (pitch 132 floats).
// ---------------------------------------------------------------------------
#define ZPITCH 132

__global__ __launch_bounds__(256, 2) void out_mma(const float* __restrict__ x1,
                                                  const float* __restrict__ x2,
                                                  float* __restrict__ out) {
    extern __shared__ char sm[];
    const uint32_t smb = smem_u32(sm);
    const int t = threadIdx.x, w = t >> 5, l = t & 31;
    const int nblk = blockIdx.x, cblk = blockIdx.y, b = blockIdx.z;
    const int n0 = nblk * 128, c0 = cblk * 128;

    const bf16* A1g = g_A1 + (size_t)(b * CH + c0) * CH;
    const bf16* A2g = g_A2 + (size_t)(b * CH + c0) * CH;
    const bf16* B1g = g_rT1 + ((size_t)b * NPIX + n0) * CH;
    const bf16* B2g = g_rT2 + ((size_t)b * NPIX + n0) * CH;

    float acc[4][4][4] = {};
    gemm_mainloop(A1g, CH, B1g, CH, CH / 32, smb, acc);
    gemm_mainloop(A2g, CH, B2g, CH, CH / 32, smb, acc);

    const int mw0 = (w >> 2) * 64, nw0 = (w & 3) * 32;
    const int rr = l >> 2, cc = (l & 3) * 2;
    float* Zs = (float*)sm;          // [64 n][ZPITCH c]

    #pragma unroll 1
    for (int h = 0; h < 2; h++) {
        // warps whose n-range falls in this half stage their fragments
        if ((nw0 >> 6) == h) {
            const int nb = nw0 - h * 64;
            #pragma unroll
            for (int i = 0; i < 4; i++)
                #pragma unroll
                for (int j = 0; j < 4; j++) {
                    const int cl = mw0 + i * 16 + rr;
                    const int nl = nb + j * 8 + cc;
                    Zs[(size_t)nl * ZPITCH + cl]           = acc[i][j][0];
                    Zs[(size_t)(nl + 1) * ZPITCH + cl]     = acc[i][j][1];
                    Zs[(size_t)nl * ZPITCH + cl + 8]       = acc[i][j][2];
                    Zs[(size_t)(nl + 1) * ZPITCH + cl + 8] = acc[i][j][3];
                }
        }
        __syncthreads();
        // coalesced residual write: 64 n-rows x 128 c
        #pragma unroll
        for (int p = 0; p < 8; p++) {
            const int idx = t + p * 256;
            const int n = idx >> 5, c4 = (idx & 31) * 4;
            const float4 z = *(const float4*)&Zs[(size_t)n * ZPITCH + c4];
            const size_t g = (size_t)b * CN + (size_t)(n0 + h * 64 + n) * CH + c0 + c4;
            const float4 a = *(const float4*)(x1 + g);
            const float4 bb = *(const float4*)(x2 + g);
            float4 o;
            o.x = z.x + a.x + bb.x; o.y = z.y + a.y + bb.y;
            o.z = z.z + a.z + bb.z; o.w = z.w + a.w + bb.w;
            *(float4*)(out + g) = o;
        }
        __syncthreads();
    }
}

// ---------------------------------------------------------------------------
extern "C" void kernel_launch(void* const* d_in, const int* in_sizes, int n_in,
                              void* d_out, int out_size) {
    (void)in_sizes; (void)n_in; (void)out_size;
    const float* x1 = (const float*)d_in[0];
    const float* x2 = (const float*)d_in[1];
    float* out = (float*)d_out;

    cudaFuncSetAttribute(gram_mma, cudaFuncAttributeMaxDynamicSharedMemorySize, SM_MAIN);
    cudaFuncSetAttribute(out_mma,  cudaFuncAttributeMaxDynamicSharedMemorySize, SM_MAIN);

    norms_kernel<<<BATCH * CH, 256>>>(x1, x2);
    convert_kernel<<<dim3(64, 4, BATCH), 256>>>(x1, x2);
    gram_mma<<<dim3(2, 2, BATCH * 2), 256, SM_MAIN>>>();
    softmax_kernel<<<BATCH * CH, 256>>>();
    out_mma<<<dim3(32, 2, BATCH), 256, SM_MAIN>>>(x1, x2, out);
}

// round 7
// speedup vs baseline: 5.5566x; 1.3033x over previous
#include <cuda_runtime.h>
#include <cuda_bf16.h>
#include <math.h>
#include <stdint.h>

#define BATCH 16
#define CH    256
#define NPIX  4096
#define CN    (CH * NPIX)

typedef __nv_bfloat16 bf16;

// ---------------- device-global scratch (allocation-free) ----------------
__device__ float g_inv1[BATCH * CH];
__device__ float g_inv2[BATCH * CH];
__device__ __align__(16) bf16 g_s [BATCH * CN];   // inv1*x1+inv2*x2 [b][c][n]
__device__ __align__(16) bf16 g_r1[BATCH * CN];   // raw bf16 x1     [b][c][n]
__device__ __align__(16) bf16 g_r2[BATCH * CN];   // raw bf16 x2     [b][c][n]
__device__ __align__(16) float g_Sp[4][BATCH * CH * CH]; // partials [mat*2+ks]
__device__ __align__(16) bf16 g_A1[BATCH * CH * CH];     // bf16 probs
__device__ __align__(16) bf16 g_A2[BATCH * CH * CH];

// ---------------- PTX helpers (family-portable: sm_80+ baseline) ----------
__device__ __forceinline__ uint32_t smem_u32(const void* p) {
    uint32_t a;
    asm("{ .reg .u64 t; cvta.to.shared.u64 t, %1; cvt.u32.u64 %0, t; }" : "=r"(a) : "l"(p));
    return a;
}
__device__ __forceinline__ void cpasync16(uint32_t s, const void* g) {
    asm volatile("cp.async.cg.shared.global [%0], [%1], 16;" :: "r"(s), "l"(g));
}
#define CP_COMMIT() asm volatile("cp.async.commit_group;")
#define CP_WAIT(N)  asm volatile("cp.async.wait_group %0;" :: "n"(N))

__device__ __forceinline__ void ldm_x4(uint32_t* r, uint32_t a) {
    asm volatile("ldmatrix.sync.aligned.m8n8.x4.shared.b16 {%0,%1,%2,%3}, [%4];"
        : "=r"(r[0]), "=r"(r[1]), "=r"(r[2]), "=r"(r[3]) : "r"(a));
}
__device__ __forceinline__ void ldm_x4t(uint32_t* r, uint32_t a) {
    asm volatile("ldmatrix.sync.aligned.m8n8.x4.trans.shared.b16 {%0,%1,%2,%3}, [%4];"
        : "=r"(r[0]), "=r"(r[1]), "=r"(r[2]), "=r"(r[3]) : "r"(a));
}
__device__ __forceinline__ void mma16816(float* c, const uint32_t* a, const uint32_t* b) {
    asm volatile("mma.sync.aligned.m16n8k16.row.col.f32.bf16.bf16.f32 "
        "{%0,%1,%2,%3}, {%4,%5,%6,%7}, {%8,%9}, {%0,%1,%2,%3};"
        : "+f"(c[0]), "+f"(c[1]), "+f"(c[2]), "+f"(c[3])
        : "r"(a[0]), "r"(a[1]), "r"(a[2]), "r"(a[3]), "r"(b[0]), "r"(b[1]));
}

// A/B tiles 128 rows x 32 bf16, padded row = 80 B.
#define ROW_B   80
#define TILE_B  (128 * ROW_B)        // 10240 B
#define STAGE_B (2 * TILE_B)         // 20480 B
#define PIPE    3
#define SM_MAIN (PIPE * STAGE_B)     // 61440 B
// out-kernel B tile: [32 k][128 n] bf16, pitch 272 B (17x16B, conflict-free)
#define BROW_B   272
#define BTILE_B  (32 * BROW_B)       // 8704 B
#define OSTAGE_B (TILE_B + BTILE_B)  // 18944 B
#define SM_OUT   (PIPE * OSTAGE_B)   // 56832 B

// ---------------------------------------------------------------------------
// Mainloop 1 (gram): C[128m x 128n] += A[m,k]*B[n,k]^T, both row-major [rows][k].
// ---------------------------------------------------------------------------
__device__ __forceinline__ void gemm_mainloop(const bf16* __restrict__ Ag, int lda,
                                              const bf16* __restrict__ Bg, int ldb,
                                              int niter, uint32_t smb,
                                              float acc[4][4][4]) {
    const int t = threadIdx.x;
    const int w = t >> 5, l = t & 31;
    const int mw0 = (w >> 2) * 64, nw0 = (w & 3) * 32;
    const int fr  = t >> 2;
    const int fkB = (t & 3) * 16;
    const int fkE = (t & 3) * 8;
    const int lA_row = l & 15, lA_k = (l >> 4) * 8;
    const int q = l >> 3;
    const int lB_row = ((q >> 1) * 8) + (l & 7);
    const int lB_k = (q & 1) * 8;

    #pragma unroll
    for (int s = 0; s < PIPE - 1; s++) {
        const int k0 = s * 32;
        const uint32_t st = smb + s * STAGE_B;
        const bf16* ga = Ag + (size_t)fr * lda + k0 + fkE;
        const bf16* gb = Bg + (size_t)fr * ldb + k0 + fkE;
        const uint32_t sa = st + fr * ROW_B + fkB;
        const uint32_t sb = st + TILE_B + fr * ROW_B + fkB;
        cpasync16(sa, ga);
        cpasync16(sa + 64 * ROW_B, ga + (size_t)64 * lda);
        cpasync16(sb, gb);
        cpasync16(sb + 64 * ROW_B, gb + (size_t)64 * ldb);
        CP_COMMIT();
    }

    int stage = 0, nstage = PIPE - 1;
    #pragma unroll 1
    for (int it = 0; it < niter; it++) {
        if (it + PIPE - 1 < niter) {
            const int k0 = (it + PIPE - 1) * 32;
            const uint32_t st = smb + nstage * STAGE_B;
            const bf16* ga = Ag + (size_t)fr * lda + k0 + fkE;
            const bf16* gb = Bg + (size_t)fr * ldb + k0 + fkE;
            const uint32_t sa = st + fr * ROW_B + fkB;
            const uint32_t sb = st + TILE_B + fr * ROW_B + fkB;
            cpasync16(sa, ga);
            cpasync16(sa + 64 * ROW_B, ga + (size_t)64 * lda);
            cpasync16(sb, gb);
            cpasync16(sb + 64 * ROW_B, gb + (size_t)64 * ldb);
            CP_COMMIT();
            CP_WAIT(PIPE - 1);
            if (++nstage == PIPE) nstage = 0;
        } else {
            CP_WAIT(0);
        }
        __syncthreads();

        const uint32_t Abase = smb + stage * STAGE_B;
        const uint32_t Bbase = Abase + TILE_B;
        if (++stage == PIPE) stage = 0;
        #pragma unroll
        for (int ks = 0; ks < 2; ks++) {
            uint32_t afr[4][4], bfr[4][2];
            #pragma unroll
            for (int i = 0; i < 4; i++)
                ldm_x4(afr[i], Abase + (mw0 + i * 16 + lA_row) * ROW_B
                                     + (ks * 16 + lA_k) * 2);
            #pragma unroll
            for (int p = 0; p < 2; p++) {
                uint32_t r[4];
                ldm_x4(r, Bbase + (nw0 + p * 16 + lB_row) * ROW_B
                                + (ks * 16 + lB_k) * 2);
                bfr[p * 2][0] = r[0]; bfr[p * 2][1] = r[1];
                bfr[p * 2 + 1][0] = r[2]; bfr[p * 2 + 1][1] = r[3];
            }
            #pragma unroll
            for (int i = 0; i < 4; i++)
                #pragma unroll
                for (int j = 0; j < 4; j++)
                    mma16816(acc[i][j], afr[i], bfr[j]);
        }
        __syncthreads();
    }
}

// ---------------------------------------------------------------------------
// Mainloop 2 (out): B is [k][n] row-major in gmem (ldb = NPIX); loaded into
// [32k][128n] smem tiles and fetched with ldmatrix.trans.
// ---------------------------------------------------------------------------
__device__ __forceinline__ void gemm_mainloop_tb(const bf16* __restrict__ Ag, int lda,
                                                 const bf16* __restrict__ Bg, int ldb,
                                                 int niter, uint32_t smb,
                                                 float acc[4][4][4]) {
    const int t = threadIdx.x;
    const int w = t >> 5, l = t & 31;
    const int mw0 = (w >> 2) * 64, nw0 = (w & 3) * 32;
    const int fr  = t >> 2;
    const int fkB = (t & 3) * 16;
    const int fkE = (t & 3) * 8;
    const int lA_row = l & 15, lA_k = (l >> 4) * 8;
    const int q = l >> 3;
    // B fill coords: thread covers chunks t and t+256
    const int br0 = t >> 4, bc0 = (t & 15);

    #pragma unroll
    for (int s = 0; s < PIPE - 1; s++) {
        const int k0 = s * 32;
        const uint32_t st = smb + s * OSTAGE_B;
        const bf16* ga = Ag + (size_t)fr * lda + k0 + fkE;
        const uint32_t sa = st + fr * ROW_B + fkB;
        cpasync16(sa, ga);
        cpasync16(sa + 64 * ROW_B, ga + (size_t)64 * lda);
        const uint32_t sbb = st + TILE_B;
        cpasync16(sbb + br0 * BROW_B + bc0 * 16,
                  Bg + (size_t)(k0 + br0) * ldb + bc0 * 8);
        cpasync16(sbb + (br0 + 16) * BROW_B + bc0 * 16,
                  Bg + (size_t)(k0 + br0 + 16) * ldb + bc0 * 8);
        CP_COMMIT();
    }

    int stage = 0, nstage = PIPE - 1;
    #pragma unroll 1
    for (int it = 0; it < niter; it++) {
        if (it + PIPE - 1 < niter) {
            const int k0 = (it + PIPE - 1) * 32;
            const uint32_t st = smb + nstage * OSTAGE_B;
            const bf16* ga = Ag + (size_t)fr * lda + k0 + fkE;
            const uint32_t sa = st + fr * ROW_B + fkB;
            cpasync16(sa, ga);
            cpasync16(sa + 64 * ROW_B, ga + (size_t)64 * lda);
            const uint32_t sbb = st + TILE_B;
            cpasync16(sbb + br0 * BROW_B + bc0 * 16,
                      Bg + (size_t)(k0 + br0) * ldb + bc0 * 8);
            cpasync16(sbb + (br0 + 16) * BROW_B + bc0 * 16,
                      Bg + (size_t)(k0 + br0 + 16) * ldb + bc0 * 8);
            CP_COMMIT();
            CP_WAIT(PIPE - 1);
            if (++nstage == PIPE) nstage = 0;
        } else {
            CP_WAIT(0);
        }
        __syncthreads();

        const uint32_t Abase = smb + stage * OSTAGE_B;
        const uint32_t Bbase = Abase + TILE_B;
        if (++stage == PIPE) stage = 0;
        #pragma unroll
        for (int ks = 0; ks < 2; ks++) {
            uint32_t afr[4][4], bfr[4][2];
            #pragma unroll
            for (int i = 0; i < 4; i++)
                ldm_x4(afr[i], Abase + (mw0 + i * 16 + lA_row) * ROW_B
                                     + (ks * 16 + lA_k) * 2);
            #pragma unroll
            for (int p = 0; p < 2; p++) {
                uint32_t r[4];
                // trans: address row = k, col = n
                ldm_x4t(r, Bbase + (ks * 16 + (q & 1) * 8 + (l & 7)) * BROW_B
                                 + (nw0 + p * 16 + (q >> 1) * 8) * 2);
                bfr[p * 2][0] = r[0]; bfr[p * 2][1] = r[1];
                bfr[p * 2 + 1][0] = r[2]; bfr[p * 2 + 1][1] = r[3];
            }
            #pragma unroll
            for (int i = 0; i < 4; i++)
                #pragma unroll
                for (int j = 0; j < 4; j++)
                    mma16816(acc[i][j], afr[i], bfr[j]);
        }
        __syncthreads();
    }
}

// ---------------------------------------------------------------------------
// Kernel 1: fused norms + bf16 conversion. One CTA per (b,c) row; the row is
// held in registers between the reduction and the converted writes.
// ---------------------------------------------------------------------------
__global__ __launch_bounds__(256) void normconv_kernel(const float* __restrict__ x1,
                                                       const float* __restrict__ x2) {
    const int row = blockIdx.x;                     // b*CH + c
    const int t = threadIdx.x;
    const size_t base = (size_t)row * NPIX;
    float4 va[4], vb[4];
    float s1 = 0.f, s2 = 0.f;
    #pragma unroll
    for (int p = 0; p < 4; p++) {
        va[p] = *(const float4*)(x1 + base + (size_t)(p * 256 + t) * 4);
        vb[p] = *(const float4*)(x2 + base + (size_t)(p * 256 + t) * 4);
        s1 += va[p].x * va[p].x + va[p].y * va[p].y + va[p].z * va[p].z + va[p].w * va[p].w;
        s2 += vb[p].x * vb[p].x + vb[p].y * vb[p].y + vb[p].z * vb[p].z + vb[p].w * vb[p].w;
    }
    __shared__ float sh1[8], sh2[8];
    const int lane = t & 31, w = t >> 5;
    #pragma unroll
    for (int o = 16; o; o >>= 1) {
        s1 += __shfl_xor_sync(0xffffffffu, s1, o);
        s2 += __shfl_xor_sync(0xffffffffu, s2, o);
    }
    if (lane == 0) { sh1[w] = s1; sh2[w] = s2; }
    __syncthreads();
    float t1 = 0.f, t2 = 0.f;
    #pragma unroll
    for (int i = 0; i < 8; i++) { t1 += sh1[i]; t2 += sh2[i]; }
    const float i1 = 1.f / fmaxf(sqrtf(t1), 1e-12f);
    const float i2 = 1.f / fmaxf(sqrtf(t2), 1e-12f);
    if (t == 0) { g_inv1[row] = i1; g_inv2[row] = i2; }

    #pragma unroll
    for (int p = 0; p < 4; p++) {
        const size_t off = base + (size_t)(p * 256 + t) * 4;
        const float a[4]  = {va[p].x, va[p].y, va[p].z, va[p].w};
        const float bb[4] = {vb[p].x, vb[p].y, vb[p].z, vb[p].w};
        bf16 sv[4], r1v[4], r2v[4];
        #pragma unroll
        for (int i = 0; i < 4; i++) {
            sv[i]  = __float2bfloat16(i1 * a[i] + i2 * bb[i]);
            r1v[i] = __float2bfloat16(a[i]);
            r2v[i] = __float2bfloat16(bb[i]);
        }
        *(uint2*)(g_s  + off) = *(const uint2*)sv;
        *(uint2*)(g_r1 + off) = *(const uint2*)r1v;
        *(uint2*)(g_r2 + off) = *(const uint2*)r2v;
    }
}

// ---------------------------------------------------------------------------
// Kernel 2: gram HMMA, split-K=2. Raw partials (no inv scaling here).
// grid (2 dblk, 2 cblk, B*4): z = b*4 + mat*2 + ks.
// ---------------------------------------------------------------------------
__global__ __launch_bounds__(256, 2) void gram_mma() {
    extern __shared__ char sm[];
    const uint32_t smb = smem_u32(sm);
    const int t = threadIdx.x, w = t >> 5, l = t & 31;
    const int dblk = blockIdx.x, cblk = blockIdx.y;
    const int zi = blockIdx.z;
    const int b = zi >> 2, mat = (zi >> 1) & 1, ks = zi & 1;

    const bf16* Ag = g_s + (size_t)b * CN + (size_t)(cblk * 128) * NPIX + ks * 2048;
    const bf16* Bg = (mat ? g_r2 : g_r1) + (size_t)b * CN
                   + (size_t)(dblk * 128) * NPIX + ks * 2048;

    float acc[4][4][4] = {};
    gemm_mainloop(Ag, NPIX, Bg, NPIX, 2048 / 32, smb, acc);

    float* S = g_Sp[mat * 2 + ks] + (size_t)(b * CH + cblk * 128) * CH + dblk * 128;
    const int mw0 = (w >> 2) * 64, nw0 = (w & 3) * 32;
    const int rr = l >> 2, cc = (l & 3) * 2;
    #pragma unroll
    for (int i = 0; i < 4; i++)
        #pragma unroll
        for (int j = 0; j < 4; j++) {
            const int c_ = mw0 + i * 16 + rr;
            const int d_ = nw0 + j * 8 + cc;
            float2 lo = {acc[i][j][0], acc[i][j][1]};
            float2 hi = {acc[i][j][2], acc[i][j][3]};
            *(float2*)&S[(size_t)c_ * CH + d_] = lo;
            *(float2*)&S[(size_t)(c_ + 8) * CH + d_] = hi;
        }
}

// ---------------------------------------------------------------------------
// Kernel 3: softmax. Sums split-K partials, applies inv[d], emits bf16 probs.
// ---------------------------------------------------------------------------
__global__ __launch_bounds__(256) void softmax_kernel() {
    const int row = blockIdx.x;                  // b*CH + c
    const int t = threadIdx.x;
    const int lane = t & 31, w = t >> 5;
    __shared__ float sh1[8], sh2[8];
    const size_t base = (size_t)row * CH;
    const int invb = (row >> 8) << 8;            // b*CH
    const float v1 = (g_Sp[0][base + t] + g_Sp[1][base + t]) * g_inv1[invb + t];
    const float v2 = (g_Sp[2][base + t] + g_Sp[3][base + t]) * g_inv2[invb + t];

    float m1 = v1, m2 = v2;
    #pragma unroll
    for (int o = 16; o; o >>= 1) {
        m1 = fmaxf(m1, __shfl_xor_sync(0xffffffffu, m1, o));
        m2 = fmaxf(m2, __shfl_xor_sync(0xffffffffu, m2, o));
    }
    if (lane == 0) { sh1[w] = m1; sh2[w] = m2; }
    __syncthreads();
    m1 = sh1[0]; m2 = sh2[0];
    #pragma unroll
    for (int i = 1; i < 8; i++) { m1 = fmaxf(m1, sh1[i]); m2 = fmaxf(m2, sh2[i]); }

    const float e1 = __expf(v1 - m1);
    const float e2 = __expf(v2 - m2);
    __syncthreads();

    float s1 = e1, s2 = e2;
    #pragma unroll
    for (int o = 16; o; o >>= 1) {
        s1 += __shfl_xor_sync(0xffffffffu, s1, o);
        s2 += __shfl_xor_sync(0xffffffffu, s2, o);
    }
    if (lane == 0) { sh1[w] = s1; sh2[w] = s2; }
    __syncthreads();
    s1 = 0.f; s2 = 0.f;
    #pragma unroll
    for (int i = 0; i < 8; i++) { s1 += sh1[i]; s2 += sh2[i]; }

    g_A1[base + t] = __float2bfloat16(e1 / s1);
    g_A2[base + t] = __float2bfloat16(e2 / s2);
}

// ---------------------------------------------------------------------------
// Kernel 4: back-projection HMMA (trans-B from raw r1/r2) + residual.
// grid (32 nblk, 2 cblk, B).
// ---------------------------------------------------------------------------
#define ZPITCH 132

__global__ __launch_bounds__(256, 2) void out_mma(const float* __restrict__ x1,
                                                  const float* __restrict__ x2,
                                                  float* __restrict__ out) {
    extern __shared__ char sm[];
    const uint32_t smb = smem_u32(sm);
    const int t = threadIdx.x, w = t >> 5, l = t & 31;
    const int nblk = blockIdx.x, cblk = blockIdx.y, b = blockIdx.z;
    const int n0 = nblk * 128, c0 = cblk * 128;

    const bf16* A1g = g_A1 + (size_t)(b * CH + c0) * CH;
    const bf16* A2g = g_A2 + (size_t)(b * CH + c0) * CH;
    const bf16* B1g = g_r1 + (size_t)b * CN + n0;   // [d][n], ldb = NPIX
    const bf16* B2g = g_r2 + (size_t)b * CN + n0;

    float acc[4][4][4] = {};
    gemm_mainloop_tb(A1g, CH, B1g, NPIX, CH / 32, smb, acc);
    gemm_mainloop_tb(A2g, CH, B2g, NPIX, CH / 32, smb, acc);

    const int mw0 = (w >> 2) * 64, nw0 = (w & 3) * 32;
    const int rr = l >> 2, cc = (l & 3) * 2;
    float* Zs = (float*)sm;          // [64 n][ZPITCH c]

    #pragma unroll 1
    for (int h = 0; h < 2; h++) {
        if ((nw0 >> 6) == h) {
            const int nb = nw0 - h * 64;
            #pragma unroll
            for (int i = 0; i < 4; i++)
                #pragma unroll
                for (int j = 0; j < 4; j++) {
                    const int cl = mw0 + i * 16 + rr;
                    const int nl = nb + j * 8 + cc;
                    Zs[(size_t)nl * ZPITCH + cl]           = acc[i][j][0];
                    Zs[(size_t)(nl + 1) * ZPITCH + cl]     = acc[i][j][1];
                    Zs[(size_t)nl * ZPITCH + cl + 8]       = acc[i][j][2];
                    Zs[(size_t)(nl + 1) * ZPITCH + cl + 8] = acc[i][j][3];
                }
        }
        __syncthreads();
        #pragma unroll
        for (int p = 0; p < 8; p++) {
            const int idx = t + p * 256;
            const int n = idx >> 5, c4 = (idx & 31) * 4;
            const float4 z = *(const float4*)&Zs[(size_t)n * ZPITCH + c4];
            const size_t g = (size_t)b * CN + (size_t)(n0 + h * 64 + n) * CH + c0 + c4;
            const float4 a = *(const float4*)(x1 + g);
            const float4 bb = *(const float4*)(x2 + g);
            float4 o;
            o.x = z.x + a.x + bb.x; o.y = z.y + a.y + bb.y;
            o.z = z.z + a.z + bb.z; o.w = z.w + a.w + bb.w;
            *(float4*)(out + g) = o;
        }
        __syncthreads();
    }
}

// ---------------------------------------------------------------------------
extern "C" void kernel_launch(void* const* d_in, const int* in_sizes, int n_in,
                              void* d_out, int out_size) {
    (void)in_sizes; (void)n_in; (void)out_size;
    const float* x1 = (const float*)d_in[0];
    const float* x2 = (const float*)d_in[1];
    float* out = (float*)d_out;

    cudaFuncSetAttribute(gram_mma, cudaFuncAttributeMaxDynamicSharedMemorySize, SM_MAIN);
    cudaFuncSetAttribute(out_mma,  cudaFuncAttributeMaxDynamicSharedMemorySize, SM_OUT);

    normconv_kernel<<<BATCH * CH, 256>>>(x1, x2);
    gram_mma<<<dim3(2, 2, BATCH * 4), 256, SM_MAIN>>>();
    softmax_kernel<<<BATCH * CH, 256>>>();
    out_mma<<<dim3(32, 2, BATCH), 256, SM_OUT>>>(x1, x2, out);
}

// round 9
// speedup vs baseline: 5.7146x; 1.0284x over previous
#include <cuda_runtime.h>
#include <cuda_bf16.h>
#include <math.h>
#include <stdint.h>

#define BATCH 16
#define CH    256
#define NPIX  4096
#define CN    (CH * NPIX)

typedef __nv_bfloat16 bf16;

// ---------------- device-global scratch (allocation-free) ----------------
__device__ float g_inv1[BATCH * CH];
__device__ float g_inv2[BATCH * CH];
__device__ __align__(16) bf16 g_s [BATCH * CN];   // inv1*x1+inv2*x2 [b][c][n]
__device__ __align__(16) bf16 g_r1[BATCH * CN];   // raw bf16 x1     [b][c][n]
__device__ __align__(16) bf16 g_r2[BATCH * CN];   // raw bf16 x2     [b][c][n]
__device__ __align__(16) float g_Sp[4][BATCH * CH * CH]; // partials [mat*2+ks]
__device__ __align__(16) bf16 g_A1[BATCH * CH * CH];     // bf16 probs
__device__ __align__(16) bf16 g_A2[BATCH * CH * CH];

// ---------------- PTX helpers (family-portable: sm_80+ baseline) ----------
__device__ __forceinline__ uint32_t smem_u32(const void* p) {
    uint32_t a;
    asm("{ .reg .u64 t; cvta.to.shared.u64 t, %1; cvt.u32.u64 %0, t; }" : "=r"(a) : "l"(p));
    return a;
}
__device__ __forceinline__ void cpasync16(uint32_t s, const void* g) {
    asm volatile("cp.async.cg.shared.global [%0], [%1], 16;" :: "r"(s), "l"(g));
}
#define CP_COMMIT() asm volatile("cp.async.commit_group;")
#define CP_WAIT(N)  asm volatile("cp.async.wait_group %0;" :: "n"(N))

__device__ __forceinline__ void ldm_x4(uint32_t* r, uint32_t a) {
    asm volatile("ldmatrix.sync.aligned.m8n8.x4.shared.b16 {%0,%1,%2,%3}, [%4];"
        : "=r"(r[0]), "=r"(r[1]), "=r"(r[2]), "=r"(r[3]) : "r"(a));
}
__device__ __forceinline__ void ldm_x4t(uint32_t* r, uint32_t a) {
    asm volatile("ldmatrix.sync.aligned.m8n8.x4.trans.shared.b16 {%0,%1,%2,%3}, [%4];"
        : "=r"(r[0]), "=r"(r[1]), "=r"(r[2]), "=r"(r[3]) : "r"(a));
}
__device__ __forceinline__ void mma16816(float* c, const uint32_t* a, const uint32_t* b) {
    asm volatile("mma.sync.aligned.m16n8k16.row.col.f32.bf16.bf16.f32 "
        "{%0,%1,%2,%3}, {%4,%5,%6,%7}, {%8,%9}, {%0,%1,%2,%3};"
        : "+f"(c[0]), "+f"(c[1]), "+f"(c[2]), "+f"(c[3])
        : "r"(a[0]), "r"(a[1]), "r"(a[2]), "r"(a[3]), "r"(b[0]), "r"(b[1]));
}

// A/B tiles 128 rows x 32 bf16, padded row = 80 B.
#define ROW_B   80
#define TILE_B  (128 * ROW_B)        // 10240 B
#define STAGE_B (2 * TILE_B)         // 20480 B
#define PIPE    4
#define SM_MAIN (PIPE * STAGE_B)     // 81920 B
// out-kernel B tile: [32 k][128 n] bf16, pitch 272 B (17x16B, conflict-free)
#define BROW_B   272
#define BTILE_B  (32 * BROW_B)       // 8704 B
#define OSTAGE_B (TILE_B + BTILE_B)  // 18944 B
#define SM_OUT   (PIPE * OSTAGE_B)   // 75776 B

// ---------------------------------------------------------------------------
// Stage fills
// ---------------------------------------------------------------------------
__device__ __forceinline__ void fill_gram(const bf16* __restrict__ Ag, int lda,
                                          const bf16* __restrict__ Bg, int ldb,
                                          int k0, uint32_t st,
                                          int fr, int fkB, int fkE) {
    const bf16* ga = Ag + (size_t)fr * lda + k0 + fkE;
    const bf16* gb = Bg + (size_t)fr * ldb + k0 + fkE;
    const uint32_t sa = st + fr * ROW_B + fkB;
    const uint32_t sb = st + TILE_B + fr * ROW_B + fkB;
    cpasync16(sa, ga);
    cpasync16(sa + 64 * ROW_B, ga + (size_t)64 * lda);
    cpasync16(sb, gb);
    cpasync16(sb + 64 * ROW_B, gb + (size_t)64 * ldb);
}

__device__ __forceinline__ void fill_tb(const bf16* __restrict__ Ag, int lda,
                                        const bf16* __restrict__ Bg, int ldb,
                                        int k0, uint32_t st,
                                        int fr, int fkB, int fkE,
                                        int br0, int bc0) {
    const bf16* ga = Ag + (size_t)fr * lda + k0 + fkE;
    const uint32_t sa = st + fr * ROW_B + fkB;
    cpasync16(sa, ga);
    cpasync16(sa + 64 * ROW_B, ga + (size_t)64 * lda);
    const uint32_t sbb = st + TILE_B;
    cpasync16(sbb + br0 * BROW_B + bc0 * 16,
              Bg + (size_t)(k0 + br0) * ldb + bc0 * 8);
    cpasync16(sbb + (br0 + 16) * BROW_B + bc0 * 16,
              Bg + (size_t)(k0 + br0 + 16) * ldb + bc0 * 8);
}

// ---------------------------------------------------------------------------
// Compute one 32-k stage (both mainloops share this shape).
// ---------------------------------------------------------------------------
__device__ __forceinline__ void compute_stage(uint32_t Abase, uint32_t Bbase,
                                              int mw0, int nw0, int lA_row, int lA_k,
                                              int lB_row, int lB_k,
                                              float acc[4][4][4]) {
    #pragma unroll
    for (int ks = 0; ks < 2; ks++) {
        uint32_t afr[4][4], bfr[4][2];
        #pragma unroll
        for (int i = 0; i < 4; i++)
            ldm_x4(afr[i], Abase + (mw0 + i * 16 + lA_row) * ROW_B
                                 + (ks * 16 + lA_k) * 2);
        #pragma unroll
        for (int p = 0; p < 2; p++) {
            uint32_t r[4];
            ldm_x4(r, Bbase + (nw0 + p * 16 + lB_row) * ROW_B
                            + (ks * 16 + lB_k) * 2);
            bfr[p * 2][0] = r[0]; bfr[p * 2][1] = r[1];
            bfr[p * 2 + 1][0] = r[2]; bfr[p * 2 + 1][1] = r[3];
        }
        #pragma unroll
        for (int i = 0; i < 4; i++)
            #pragma unroll
            for (int j = 0; j < 4; j++)
                mma16816(acc[i][j], afr[i], bfr[j]);
    }
}

__device__ __forceinline__ void compute_stage_tb(uint32_t Abase, uint32_t Bbase,
                                                 int mw0, int nw0, int lA_row, int lA_k,
                                                 int q, int l,
                                                 float acc[4][4][4]) {
    #pragma unroll
    for (int ks = 0; ks < 2; ks++) {
        uint32_t afr[4][4], bfr[4][2];
        #pragma unroll
        for (int i = 0; i < 4; i++)
            ldm_x4(afr[i], Abase + (mw0 + i * 16 + lA_row) * ROW_B
                                 + (ks * 16 + lA_k) * 2);
        #pragma unroll
        for (int p = 0; p < 2; p++) {
            uint32_t r[4];
            ldm_x4t(r, Bbase + (ks * 16 + (q & 1) * 8 + (l & 7)) * BROW_B
                             + (nw0 + p * 16 + (q >> 1) * 8) * 2);
            bfr[p * 2][0] = r[0]; bfr[p * 2][1] = r[1];
            bfr[p * 2 + 1][0] = r[2]; bfr[p * 2 + 1][1] = r[3];
        }
        #pragma unroll
        for (int i = 0; i < 4; i++)
            #pragma unroll
            for (int j = 0; j < 4; j++)
                mma16816(acc[i][j], afr[i], bfr[j]);
    }
}

// ---------------------------------------------------------------------------
// Kernel 1: fused norms + bf16 conversion.
// ---------------------------------------------------------------------------
__global__ __launch_bounds__(256) void normconv_kernel(const float* __restrict__ x1,
                                                       const float* __restrict__ x2) {
    const int row = blockIdx.x;                     // b*CH + c
    const int t = threadIdx.x;
    const size_t base = (size_t)row * NPIX;
    float4 va[4], vb[4];
    float s1 = 0.f, s2 = 0.f;
    #pragma unroll
    for (int p = 0; p < 4; p++) {
        va[p] = *(const float4*)(x1 + base + (size_t)(p * 256 + t) * 4);
        vb[p] = *(const float4*)(x2 + base + (size_t)(p * 256 + t) * 4);
        s1 += va[p].x * va[p].x + va[p].y * va[p].y + va[p].z * va[p].z + va[p].w * va[p].w;
        s2 += vb[p].x * vb[p].x + vb[p].y * vb[p].y + vb[p].z * vb[p].z + vb[p].w * vb[p].w;
    }
    __shared__ float sh1[8], sh2[8];
    const int lane = t & 31, w = t >> 5;
    #pragma unroll
    for (int o = 16; o; o >>= 1) {
        s1 += __shfl_xor_sync(0xffffffffu, s1, o);
        s2 += __shfl_xor_sync(0xffffffffu, s2, o);
    }
    if (lane == 0) { sh1[w] = s1; sh2[w] = s2; }
    __syncthreads();
    float t1 = 0.f, t2 = 0.f;
    #pragma unroll
    for (int i = 0; i < 8; i++) { t1 += sh1[i]; t2 += sh2[i]; }
    const float i1 = 1.f / fmaxf(sqrtf(t1), 1e-12f);
    const float i2 = 1.f / fmaxf(sqrtf(t2), 1e-12f);
    if (t == 0) { g_inv1[row] = i1; g_inv2[row] = i2; }

    #pragma unroll
    for (int p = 0; p < 4; p++) {
        const size_t off = base + (size_t)(p * 256 + t) * 4;
        const float a[4]  = {va[p].x, va[p].y, va[p].z, va[p].w};
        const float bb[4] = {vb[p].x, vb[p].y, vb[p].z, vb[p].w};
        bf16 sv[4], r1v[4], r2v[4];
        #pragma unroll
        for (int i = 0; i < 4; i++) {
            sv[i]  = __float2bfloat16(i1 * a[i] + i2 * bb[i]);
            r1v[i] = __float2bfloat16(a[i]);
            r2v[i] = __float2bfloat16(bb[i]);
        }
        *(uint2*)(g_s  + off) = *(const uint2*)sv;
        *(uint2*)(g_r1 + off) = *(const uint2*)r1v;
        *(uint2*)(g_r2 + off) = *(const uint2*)r2v;
    }
}

// ---------------------------------------------------------------------------
// Kernel 2: gram HMMA, split-K=2, single-sync 4-stage pipeline.
// grid (2 dblk, 2 cblk, B*4): z = b*4 + mat*2 + ks.
// ---------------------------------------------------------------------------
__global__ __launch_bounds__(256, 2) void gram_mma() {
    extern __shared__ char sm[];
    const uint32_t smb = smem_u32(sm);
    const int t = threadIdx.x, w = t >> 5, l = t & 31;
    const int dblk = blockIdx.x, cblk = blockIdx.y;
    const int zi = blockIdx.z;
    const int b = zi >> 2, mat = (zi >> 1) & 1, ks = zi & 1;

    const bf16* Ag = g_s + (size_t)b * CN + (size_t)(cblk * 128) * NPIX + ks * 2048;
    const bf16* Bg = (mat ? g_r2 : g_r1) + (size_t)b * CN
                   + (size_t)(dblk * 128) * NPIX + ks * 2048;

    const int mw0 = (w >> 2) * 64, nw0 = (w & 3) * 32;
    const int fr  = t >> 2;
    const int fkB = (t & 3) * 16;
    const int fkE = (t & 3) * 8;
    const int lA_row = l & 15, lA_k = (l >> 4) * 8;
    const int q = l >> 3;
    const int lB_row = ((q >> 1) * 8) + (l & 7);
    const int lB_k = (q & 1) * 8;

    float acc[4][4][4] = {};
    const int niter = 2048 / 32;     // 64

    #pragma unroll
    for (int s = 0; s < PIPE - 1; s++) {
        fill_gram(Ag, NPIX, Bg, NPIX, s * 32, smb + s * STAGE_B, fr, fkB, fkE);
        CP_COMMIT();
    }
    #pragma unroll 1
    for (int it = 0; it < niter; it++) {
        CP_WAIT(PIPE - 2);
        __syncthreads();
        if (it + PIPE - 1 < niter)
            fill_gram(Ag, NPIX, Bg, NPIX, (it + PIPE - 1) * 32,
                      smb + ((it + PIPE - 1) & (PIPE - 1)) * STAGE_B, fr, fkB, fkE);
        CP_COMMIT();
        const uint32_t Abase = smb + (it & (PIPE - 1)) * STAGE_B;
        compute_stage(Abase, Abase + TILE_B, mw0, nw0, lA_row, lA_k, lB_row, lB_k, acc);
    }

    float* S = g_Sp[mat * 2 + ks] + (size_t)(b * CH + cblk * 128) * CH + dblk * 128;
    const int rr = l >> 2, cc = (l & 3) * 2;
    #pragma unroll
    for (int i = 0; i < 4; i++)
        #pragma unroll
        for (int j = 0; j < 4; j++) {
            const int c_ = mw0 + i * 16 + rr;
            const int d_ = nw0 + j * 8 + cc;
            float2 lo = {acc[i][j][0], acc[i][j][1]};
            float2 hi = {acc[i][j][2], acc[i][j][3]};
            *(float2*)&S[(size_t)c_ * CH + d_] = lo;
            *(float2*)&S[(size_t)(c_ + 8) * CH + d_] = hi;
        }
}

// ---------------------------------------------------------------------------
// Kernel 3: softmax. Sums split-K partials, applies inv[d], emits bf16 probs.
// ---------------------------------------------------------------------------
__global__ __launch_bounds__(256) void softmax_kernel() {
    const int row = blockIdx.x;                  // b*CH + c
    const int t = threadIdx.x;
    const int lane = t & 31, w = t >> 5;
    __shared__ float sh1[8], sh2[8];
    const size_t base = (size_t)row * CH;
    const int invb = (row >> 8) << 8;            // b*CH
    const float v1 = (g_Sp[0][base + t] + g_Sp[1][base + t]) * g_inv1[invb + t];
    const float v2 = (g_Sp[2][base + t] + g_Sp[3][base + t]) * g_inv2[invb + t];

    float m1 = v1, m2 = v2;
    #pragma unroll
    for (int o = 16; o; o >>= 1) {
        m1 = fmaxf(m1, __shfl_xor_sync(0xffffffffu, m1, o));
        m2 = fmaxf(m2, __shfl_xor_sync(0xffffffffu, m2, o));
    }
    if (lane == 0) { sh1[w] = m1; sh2[w] = m2; }
    __syncthreads();
    m1 = sh1[0]; m2 = sh2[0];
    #pragma unroll
    for (int i = 1; i < 8; i++) { m1 = fmaxf(m1, sh1[i]); m2 = fmaxf(m2, sh2[i]); }

    const float e1 = __expf(v1 - m1);
    const float e2 = __expf(v2 - m2);
    __syncthreads();

    float s1 = e1, s2 = e2;
    #pragma unroll
    for (int o = 16; o; o >>= 1) {
        s1 += __shfl_xor_sync(0xffffffffu, s1, o);
        s2 += __shfl_xor_sync(0xffffffffu, s2, o);
    }
    if (lane == 0) { sh1[w] = s1; sh2[w] = s2; }
    __syncthreads();
    s1 = 0.f; s2 = 0.f;
    #pragma unroll
    for (int i = 0; i < 8; i++) { s1 += sh1[i]; s2 += sh2[i]; }

    g_A1[base + t] = __float2bfloat16(e1 / s1);
    g_A2[base + t] = __float2bfloat16(e2 / s2);
}

// ---------------------------------------------------------------------------
// Kernel 4: back-projection HMMA (trans-B), fused 16-iter single-sync loop.
// grid (2 cblk, 32 nblk, B).
// ---------------------------------------------------------------------------
#define ZPITCH 132

__global__ __launch_bounds__(256, 2) void out_mma(const float* __restrict__ x1,
                                                  const float* __restrict__ x2,
                                                  float* __restrict__ out) {
    extern __shared__ char sm[];
    const uint32_t smb = smem_u32(sm);
    const int t = threadIdx.x, w = t >> 5, l = t & 31;
    const int cblk = blockIdx.x, nblk = blockIdx.y, b = blockIdx.z;
    const int n0 = nblk * 128, c0 = cblk * 128;

    const bf16* Apt[2] = { g_A1 + (size_t)(b * CH + c0) * CH,
                           g_A2 + (size_t)(b * CH + c0) * CH };
    const bf16* Bpt[2] = { g_r1 + (size_t)b * CN + n0,
                           g_r2 + (size_t)b * CN + n0 };

    const int mw0 = (w >> 2) * 64, nw0 = (w & 3) * 32;
    const int fr  = t >> 2;
    const int fkB = (t & 3) * 16;
    const int fkE = (t & 3) * 8;
    const int lA_row = l & 15, lA_k = (l >> 4) * 8;
    const int q = l >> 3;
    const int br0 = t >> 4, bc0 = t & 15;

    float acc[4][4][4] = {};
    const int niter = 16;            // 2 mats x 8 k-chunks

    #pragma unroll
    for (int s = 0; s < PIPE - 1; s++) {
        fill_tb(Apt[s >> 3], CH, Bpt[s >> 3], NPIX, (s & 7) * 32,
                smb + s * OSTAGE_B, fr, fkB, fkE, br0, bc0);
        CP_COMMIT();
    }
    #pragma unroll 1
    for (int it = 0; it < niter; it++) {
        CP_WAIT(PIPE - 2);
        __syncthreads();
        if (it + PIPE - 1 < niter) {
            const int nx = it + PIPE - 1;
            fill_tb(Apt[nx >> 3], CH, Bpt[nx >> 3], NPIX, (nx & 7) * 32,
                    smb + (nx & (PIPE - 1)) * OSTAGE_B, fr, fkB, fkE, br0, bc0);
        }
        CP_COMMIT();
        const uint32_t Abase = smb + (it & (PIPE - 1)) * OSTAGE_B;
        compute_stage_tb(Abase, Abase + TILE_B, mw0, nw0, lA_row, lA_k, q, l, acc);
    }
    __syncthreads();

    const int rr = l >> 2, cc = (l & 3) * 2;
    float* Zs = (float*)sm;          // [64 n][ZPITCH c]

    #pragma unroll 1
    for (int h = 0; h < 2; h++) {
        if ((nw0 >> 6) == h) {
            const int nb = nw0 - h * 64;
            #pragma unroll
            for (int i = 0; i < 4; i++)
                #pragma unroll
                for (int j = 0; j < 4; j++) {
                    const int cl = mw0 + i * 16 + rr;
                    const int nl = nb + j * 8 + cc;
                    Zs[(size_t)nl * ZPITCH + cl]           = acc[i][j][0];
                    Zs[(size_t)(nl + 1) * ZPITCH + cl]     = acc[i][j][1];
                    Zs[(size_t)nl * ZPITCH + cl + 8]       = acc[i][j][2];
                    Zs[(size_t)(nl + 1) * ZPITCH + cl + 8] = acc[i][j][3];
                }
        }
        __syncthreads();
        #pragma unroll
        for (int p = 0; p < 8; p++) {
            const int idx = t + p * 256;
            const int n = idx >> 5, c4 = (idx & 31) * 4;
            const float4 z = *(const float4*)&Zs[(size_t)n * ZPITCH + c4];
            const size_t g = (size_t)b * CN + (size_t)(n0 + h * 64 + n) * CH + c0 + c4;
            const float4 a = *(const float4*)(x1 + g);
            const float4 bb = *(const float4*)(x2 + g);
            float4 o;
            o.x = z.x + a.x + bb.x; o.y = z.y + a.y + bb.y;
            o.z = z.z + a.z + bb.z; o.w = z.w + a.w + bb.w;
            *(float4*)(out + g) = o;
        }
        __syncthreads();
    }
}

// ---------------------------------------------------------------------------
extern "C" void kernel_launch(void* const* d_in, const int* in_sizes, int n_in,
                              void* d_out, int out_size) {
    (void)in_sizes; (void)n_in; (void)out_size;
    const float* x1 = (const float*)d_in[0];
    const float* x2 = (const float*)d_in[1];
    float* out = (float*)d_out;

    cudaFuncSetAttribute(gram_mma, cudaFuncAttributeMaxDynamicSharedMemorySize, SM_MAIN);
    cudaFuncSetAttribute(out_mma,  cudaFuncAttributeMaxDynamicSharedMemorySize, SM_OUT);

    normconv_kernel<<<BATCH * CH, 256>>>(x1, x2);
    gram_mma<<<dim3(2, 2, BATCH * 4), 256, SM_MAIN>>>();
    softmax_kernel<<<BATCH * CH, 256>>>();
    out_mma<<<dim3(2, 32, BATCH), 256, SM_OUT>>>(x1, x2, out);
}